// round 5
// baseline (speedup 1.0000x reference)
#include <cuda_runtime.h>
#include <cuda_bf16.h>
#include <cstdint>

#define MPATH 8
#define TILE_N 16
#define THREADS 256
#define EPSV 1e-8f

// smem byte offsets from 1024-aligned base
#define OFF_W    0         // 128 KB  W bf16 [256 h][256 d] rowstride 512B chunk-swizzled
#define OFF_A    131072    // 64 KB   A bf16 [128 rows = m*16+nl][256 d] same swizzle
#define OFF_B    196608    // 1 KB    bias fp32
#define OFF_NUM  197632    // 128*4 f32
#define OFF_HH   199680    // 128*4 f32
#define OFF_TT   201728    // 16*4 f32
#define SMEM_BYTES (201984 + 1024)

__device__ unsigned int Wq_g[32768];   // bf16 W row-major pairs
__device__ float att_g[800008];

__device__ __forceinline__ uint32_t s2u(const void* p){
    uint32_t a;
    asm("{ .reg .u64 t; cvta.to.shared.u64 t, %1; cvt.u32.u64 %0, t; }" : "=r"(a) : "l"(p));
    return a;
}
__device__ __forceinline__ uint32_t pbf2(float a, float b){
    __nv_bfloat162 v = __floats2bfloat162_rn(a, b);
    return *reinterpret_cast<uint32_t*>(&v);
}
__device__ __forceinline__ float tanha(float x){
    float r; asm("tanh.approx.f32 %0, %1;" : "=f"(r) : "f"(x)); return r;
}
#define LDSM4(r0,r1,r2,r3,addr) \
    asm volatile("ldmatrix.sync.aligned.m8n8.x4.shared.b16 {%0,%1,%2,%3}, [%4];" \
        : "=r"(r0), "=r"(r1), "=r"(r2), "=r"(r3) : "r"(addr))
#define MMA16816(c0,c1,c2,c3,a0,a1,a2,a3,b0,b1) \
    asm volatile("mma.sync.aligned.m16n8k16.row.col.f32.bf16.bf16.f32 " \
        "{%0,%1,%2,%3}, {%4,%5,%6,%7}, {%8,%9}, {%0,%1,%2,%3};" \
        : "+f"(c0), "+f"(c1), "+f"(c2), "+f"(c3) \
        : "r"(a0), "r"(a1), "r"(a2), "r"(a3), "r"(b0), "r"(b1))

__global__ void prep_W(const float* __restrict__ W){
    int p = blockIdx.x * blockDim.x + threadIdx.x;   // 0..32767
    int h = p >> 7, d = (p & 127) * 2;
    Wq_g[p] = pbf2(W[h * 256 + d], W[h * 256 + d + 1]);
}

__global__ __launch_bounds__(THREADS, 1)
void hete_mma_kernel(const int* __restrict__ nodes,
                     const float* __restrict__ homo,
                     const float* __restrict__ bias,
                     const float* __restrict__ out_emb,
                     int Ntot){
    extern __shared__ unsigned char smraw[];
    unsigned char* base = (unsigned char*)(((uintptr_t)smraw + 1023) & ~(uintptr_t)1023);

    const int tid   = threadIdx.x;
    const int lane  = tid & 31;
    const int wid   = tid >> 5;
    const int mwarp = wid >> 2;       // 0..1  rows mwarp*64..+63
    const int nw    = wid & 3;        // 0..3  cols nw*64..+63
    const int q     = lane & 3;
    const int rq    = lane >> 2;      // 0..7
    const int n0    = blockIdx.x * TILE_N;

    float* fB   = (float*)(base + OFF_B);
    float* sNum = (float*)(base + OFF_NUM);
    float* sHh  = (float*)(base + OFF_HH);
    float* sTT  = (float*)(base + OFF_TT);
    const uint32_t sWu = s2u(base + OFF_W);
    const uint32_t sAu = s2u(base + OFF_A);

    // ---- stage A: homo[m, n0+nl, :] fp32 -> bf16 swizzled rows (row = m*16+nl) ----
    #pragma unroll
    for (int i = 0; i < 32; i++){
        int gi = i * 256 + tid;
        int row = gi >> 6, d4 = gi & 63;
        int m = row >> 4, nl = row & 15;
        float4 v = make_float4(0.f, 0.f, 0.f, 0.f);
        if (n0 + nl < Ntot)
            v = *(const float4*)(homo + ((size_t)m * Ntot + (n0 + nl)) * 256 + d4 * 4);
        uint32_t phys = (uint32_t)(row * 512) + ((((d4 >> 1) ^ (row & 7)) << 4)) + (d4 & 1) * 8;
        uint2 o; o.x = pbf2(v.x, v.y); o.y = pbf2(v.z, v.w);
        *(uint2*)(base + OFF_A + phys) = o;
    }

    // ---- stage W (chunk-swizzled copy from pre-packed global) ----
    {
        const uint4* g = (const uint4*)Wq_g;
        #pragma unroll
        for (int i = 0; i < 32; i++){
            int idx = i * 256 + tid;
            int row = idx >> 5, c = idx & 31;
            *(uint4*)(base + OFF_W + row * 512 + ((c ^ (row & 7)) << 4)) = g[idx];
        }
    }
    fB[tid] = bias[tid];
    __syncthreads();

    // ---- ldmatrix base addresses ----
    const int arow = mwarp * 64 + (lane & 15);
    const uint32_t PA0 = (uint32_t)(arow * 512) ^
                         ((uint32_t)(((arow & 7) ^ (lane >> 4)) << 4));
    uint32_t PB[4];
    #pragma unroll
    for (int pr = 0; pr < 4; pr++){
        int brow = nw * 64 + pr * 16 + ((lane & 16) >> 1) + (lane & 7);
        int hi = (lane >> 3) & 1;
        PB[pr] = (uint32_t)(brow * 512) ^ ((uint32_t)(((brow & 7) ^ hi) << 4));
    }

    // ---- MMA mainloop: M=128 (4 t-tiles/warp) x N=64 (4 pr, 8 cols each x2) x K=256 ----
    float acc[4][4][8];
    #pragma unroll
    for (int t = 0; t < 4; t++)
        #pragma unroll
        for (int pr = 0; pr < 4; pr++)
            #pragma unroll
            for (int j = 0; j < 8; j++) acc[t][pr][j] = 0.f;

    #pragma unroll 4
    for (int kk = 0; kk < 16; kk++){
        uint32_t a[4][4];
        #pragma unroll
        for (int t = 0; t < 4; t++)
            LDSM4(a[t][0], a[t][1], a[t][2], a[t][3],
                  sAu + ((PA0 + t * 8192) ^ (kk << 5)));
        #pragma unroll
        for (int pr = 0; pr < 4; pr++){
            uint32_t b0, b1, b2, b3;
            LDSM4(b0, b1, b2, b3, sWu + (PB[pr] ^ (kk << 5)));
            #pragma unroll
            for (int t = 0; t < 4; t++){
                MMA16816(acc[t][pr][0], acc[t][pr][1], acc[t][pr][2], acc[t][pr][3],
                         a[t][0], a[t][1], a[t][2], a[t][3], b0, b1);
                MMA16816(acc[t][pr][4], acc[t][pr][5], acc[t][pr][6], acc[t][pr][7],
                         a[t][0], a[t][1], a[t][2], a[t][3], b2, b3);
            }
        }
    }

    // ---- tgt gather (fp32) + tt partials ----
    float tg[2][16];
    float tts[2] = {0.f, 0.f};
    #pragma unroll
    for (int s = 0; s < 2; s++){
        int nl = rq + s * 8;
        int gn = n0 + nl;
        if (gn < Ntot){
            const float* tp = out_emb + (size_t)nodes[gn] * 256;
            #pragma unroll
            for (int pr = 0; pr < 4; pr++){
                int cb = nw * 64 + pr * 16 + q * 2;
                float2 v0 = *(const float2*)(tp + cb);
                float2 v1 = *(const float2*)(tp + cb + 8);
                tg[s][pr * 4 + 0] = v0.x; tg[s][pr * 4 + 1] = v0.y;
                tg[s][pr * 4 + 2] = v1.x; tg[s][pr * 4 + 3] = v1.y;
                tts[s] += v0.x * v0.x + v0.y * v0.y + v1.x * v1.x + v1.y * v1.y;
            }
        } else {
            #pragma unroll
            for (int j = 0; j < 16; j++) tg[s][j] = 0.f;
        }
    }
    if (mwarp == 0){
        #pragma unroll
        for (int s = 0; s < 2; s++){
            float v = tts[s];
            v += __shfl_xor_sync(0xFFFFFFFFu, v, 1);
            v += __shfl_xor_sync(0xFFFFFFFFu, v, 2);
            if (q == 0) sTT[(rq + s * 8) * 4 + nw] = v;
        }
    }

    // ---- epilogue: bias + tanh + num/hh, quad reduce, stash per (row, nw) ----
    #pragma unroll
    for (int t = 0; t < 4; t++){
        const int mrow = mwarp * 4 + t;
        #pragma unroll
        for (int s = 0; s < 2; s++){
            float nm = 0.f, hv = 0.f;
            #pragma unroll
            for (int pr = 0; pr < 4; pr++){
                int cb = nw * 64 + pr * 16 + q * 2;
                float2 bb0 = *(const float2*)(fB + cb);
                float2 bb1 = *(const float2*)(fB + cb + 8);
                float h0 = tanha(acc[t][pr][s * 2 + 0] + bb0.x);
                float h1 = tanha(acc[t][pr][s * 2 + 1] + bb0.y);
                float h2 = tanha(acc[t][pr][4 + s * 2 + 0] + bb1.x);
                float h3 = tanha(acc[t][pr][4 + s * 2 + 1] + bb1.y);
                nm += h0 * tg[s][pr * 4 + 0] + h1 * tg[s][pr * 4 + 1]
                    + h2 * tg[s][pr * 4 + 2] + h3 * tg[s][pr * 4 + 3];
                hv += h0 * h0 + h1 * h1 + h2 * h2 + h3 * h3;
            }
            nm += __shfl_xor_sync(0xFFFFFFFFu, nm, 1);
            nm += __shfl_xor_sync(0xFFFFFFFFu, nm, 2);
            hv += __shfl_xor_sync(0xFFFFFFFFu, hv, 1);
            hv += __shfl_xor_sync(0xFFFFFFFFu, hv, 2);
            if (q == 0){
                int row = mrow * 16 + rq + s * 8;
                sNum[row * 4 + nw] = nm;
                sHh [row * 4 + nw] = hv;
            }
        }
    }

    __syncthreads();
    // ---- softmax over meta-paths, one thread per node ----
    if (tid < TILE_N && n0 + tid < Ntot){
        const int node = tid;
        float tt = sTT[node * 4] + sTT[node * 4 + 1] + sTT[node * 4 + 2] + sTT[node * 4 + 3];
        float tn = fmaxf(sqrtf(tt), EPSV);
        float cv[MPATH], mx = -1e30f;
        #pragma unroll
        for (int m = 0; m < MPATH; m++){
            int row = m * 16 + node;
            float num = sNum[row * 4] + sNum[row * 4 + 1] + sNum[row * 4 + 2] + sNum[row * 4 + 3];
            float hh  = sHh [row * 4] + sHh [row * 4 + 1] + sHh [row * 4 + 2] + sHh [row * 4 + 3];
            float hn = fmaxf(sqrtf(hh), EPSV);
            cv[m] = num / (hn * tn);
            mx = fmaxf(mx, cv[m]);
        }
        float se = 0.f;
        #pragma unroll
        for (int m = 0; m < MPATH; m++){ cv[m] = __expf(cv[m] - mx); se += cv[m]; }
        float inv = 1.f / se;
        float4 a0 = make_float4(cv[0] * inv, cv[1] * inv, cv[2] * inv, cv[3] * inv);
        float4 a1 = make_float4(cv[4] * inv, cv[5] * inv, cv[6] * inv, cv[7] * inv);
        *(float4*)(att_g + (size_t)(n0 + node) * 8)     = a0;
        *(float4*)(att_g + (size_t)(n0 + node) * 8 + 4) = a1;
    }
}

// ---------------- weighted sum (fp32 homo) ----------------
__global__ __launch_bounds__(256)
void finalize_kernel(const float* __restrict__ homo, float* __restrict__ out, int Ntot){
    const int tid = threadIdx.x;
    const int nl = tid >> 6, d4 = tid & 63;
    const int n = blockIdx.x * 4 + nl;
    if (n >= Ntot) return;
    const float4* ap = (const float4*)(att_g + (size_t)n * 8);
    float4 a0 = ap[0], a1 = ap[1];
    float att[8] = {a0.x, a0.y, a0.z, a0.w, a1.x, a1.y, a1.z, a1.w};
    float4 acc = make_float4(0.f, 0.f, 0.f, 0.f);
    #pragma unroll
    for (int m = 0; m < MPATH; m++){
        float4 v = *(const float4*)(homo + ((size_t)m * Ntot + n) * 256 + d4 * 4);
        acc.x += att[m] * v.x; acc.y += att[m] * v.y;
        acc.z += att[m] * v.z; acc.w += att[m] * v.w;
    }
    *(float4*)(out + (size_t)n * 256 + d4 * 4) = acc;
}

extern "C" void kernel_launch(void* const* d_in, const int* in_sizes, int n_in,
                              void* d_out, int out_size){
    const int*   nodes = (const int*)  d_in[0];
    const float* homo  = (const float*)d_in[1];
    const float* W     = (const float*)d_in[2];
    const float* bias  = (const float*)d_in[3];
    const float* oe    = (const float*)d_in[4];
    float* out = (float*)d_out;
    const int N = in_sizes[0];

    prep_W<<<128, 256>>>(W);

    cudaFuncSetAttribute(hete_mma_kernel,
                         cudaFuncAttributeMaxDynamicSharedMemorySize, SMEM_BYTES);
    const int nb = (N + TILE_N - 1) / TILE_N;
    hete_mma_kernel<<<nb, THREADS, SMEM_BYTES>>>(nodes, homo, bias, oe, N);

    finalize_kernel<<<(N + 3) / 4, 256>>>(homo, out, N);
}

// round 6
// speedup vs baseline: 1.2417x; 1.2417x over previous
#include <cuda_runtime.h>
#include <cuda_bf16.h>
#include <cstdint>

#define MPATH 8
#define TILE_N 16
#define THREADS 256
#define GRID 592
#define EPSV 1e-8f

// smem byte offsets from 1024-aligned base
#define OFF_W    0         // 128 KB  W bf16 [256 h][256 d] rowstride 512B chunk-swizzled
#define OFF_A    131072    // 64 KB   A bf16 [128 rows = m*16+nl][256 d] same swizzle
#define OFF_B    196608    // 1 KB    bias fp32
#define OFF_NUM  197632    // 128*4 f32
#define OFF_HH   199680    // 128*4 f32
#define OFF_TT   201728    // 16*4 f32
#define OFF_ATT  201984    // 16*8 f32
#define SMEM_BYTES (202496 + 1024)

__device__ unsigned int Wq_g[32768];   // bf16 W row-major pairs

__device__ __forceinline__ uint32_t s2u(const void* p){
    uint32_t a;
    asm("{ .reg .u64 t; cvta.to.shared.u64 t, %1; cvt.u32.u64 %0, t; }" : "=r"(a) : "l"(p));
    return a;
}
__device__ __forceinline__ uint32_t pbf2(float a, float b){
    __nv_bfloat162 v = __floats2bfloat162_rn(a, b);
    return *reinterpret_cast<uint32_t*>(&v);
}
__device__ __forceinline__ float tanha(float x){
    float r; asm("tanh.approx.f32 %0, %1;" : "=f"(r) : "f"(x)); return r;
}
#define LDSM4(r0,r1,r2,r3,addr) \
    asm volatile("ldmatrix.sync.aligned.m8n8.x4.shared.b16 {%0,%1,%2,%3}, [%4];" \
        : "=r"(r0), "=r"(r1), "=r"(r2), "=r"(r3) : "r"(addr))
#define MMA16816(c0,c1,c2,c3,a0,a1,a2,a3,b0,b1) \
    asm volatile("mma.sync.aligned.m16n8k16.row.col.f32.bf16.bf16.f32 " \
        "{%0,%1,%2,%3}, {%4,%5,%6,%7}, {%8,%9}, {%0,%1,%2,%3};" \
        : "+f"(c0), "+f"(c1), "+f"(c2), "+f"(c3) \
        : "r"(a0), "r"(a1), "r"(a2), "r"(a3), "r"(b0), "r"(b1))

__global__ void prep_W(const float* __restrict__ W){
    int p = blockIdx.x * blockDim.x + threadIdx.x;   // 0..32767
    int h = p >> 7, d = (p & 127) * 2;
    Wq_g[p] = pbf2(W[h * 256 + d], W[h * 256 + d + 1]);
}

__global__ __launch_bounds__(THREADS, 1)
void hete_fused_kernel(const int* __restrict__ nodes,
                       const float* __restrict__ homo,
                       const float* __restrict__ bias,
                       const float* __restrict__ out_emb,
                       float* __restrict__ out,
                       int Ntot){
    extern __shared__ unsigned char smraw[];
    unsigned char* base = (unsigned char*)(((uintptr_t)smraw + 1023) & ~(uintptr_t)1023);

    const int tid   = threadIdx.x;
    const int lane  = tid & 31;
    const int wid   = tid >> 5;
    const int mwarp = wid >> 2;       // 0..1  rows mwarp*64..+63
    const int nw    = wid & 3;        // 0..3  cols nw*64..+63
    const int q     = lane & 3;
    const int rq    = lane >> 2;      // 0..7

    float* fB   = (float*)(base + OFF_B);
    float* sNum = (float*)(base + OFF_NUM);
    float* sHh  = (float*)(base + OFF_HH);
    float* sTT  = (float*)(base + OFF_TT);
    float* sAtt = (float*)(base + OFF_ATT);
    const uint32_t sWu = s2u(base + OFF_W);
    const uint32_t sAu = s2u(base + OFF_A);

    // ---- stage W ONCE (chunk-swizzled copy from pre-packed global) ----
    {
        const uint4* g = (const uint4*)Wq_g;
        #pragma unroll
        for (int i = 0; i < 32; i++){
            int idx = i * 256 + tid;
            int row = idx >> 5, c = idx & 31;
            *(uint4*)(base + OFF_W + row * 512 + ((c ^ (row & 7)) << 4)) = g[idx];
        }
    }
    fB[tid] = bias[tid];

    // ---- ldmatrix base addresses (loop-invariant) ----
    const int arow = mwarp * 64 + (lane & 15);
    const uint32_t PA0 = (uint32_t)(arow * 512) ^
                         ((uint32_t)(((arow & 7) ^ (lane >> 4)) << 4));
    uint32_t PB[4];
    #pragma unroll
    for (int pr = 0; pr < 4; pr++){
        int brow = nw * 64 + pr * 16 + ((lane & 16) >> 1) + (lane & 7);
        int hi = (lane >> 3) & 1;
        PB[pr] = (uint32_t)(brow * 512) ^ ((uint32_t)(((brow & 7) ^ hi) << 4));
    }

    const int ntiles = (Ntot + TILE_N - 1) / TILE_N;

    for (int tile = blockIdx.x; tile < ntiles; tile += GRID){
        const int n0 = tile * TILE_N;

        // ---- stage A: homo[m, n0+nl, :] fp32 -> bf16 swizzled (row = m*16+nl) ----
        #pragma unroll
        for (int i = 0; i < 32; i++){
            int gi = i * 256 + tid;
            int row = gi >> 6, d4 = gi & 63;
            int m = row >> 4, nl = row & 15;
            float4 v = make_float4(0.f, 0.f, 0.f, 0.f);
            if (n0 + nl < Ntot)
                v = *(const float4*)(homo + ((size_t)m * Ntot + (n0 + nl)) * 256 + d4 * 4);
            uint32_t phys = (uint32_t)(row * 512) + ((((d4 >> 1) ^ (row & 7)) << 4)) + (d4 & 1) * 8;
            uint2 o; o.x = pbf2(v.x, v.y); o.y = pbf2(v.z, v.w);
            *(uint2*)(base + OFF_A + phys) = o;
        }
        __syncthreads();

        // ---- MMA mainloop: M=128 x N=256 x K=256 ----
        float acc[4][4][8];
        #pragma unroll
        for (int t = 0; t < 4; t++)
            #pragma unroll
            for (int pr = 0; pr < 4; pr++)
                #pragma unroll
                for (int j = 0; j < 8; j++) acc[t][pr][j] = 0.f;

        #pragma unroll 4
        for (int kk = 0; kk < 16; kk++){
            uint32_t a[4][4];
            #pragma unroll
            for (int t = 0; t < 4; t++)
                LDSM4(a[t][0], a[t][1], a[t][2], a[t][3],
                      sAu + ((PA0 + t * 8192) ^ (kk << 5)));
            #pragma unroll
            for (int pr = 0; pr < 4; pr++){
                uint32_t b0, b1, b2, b3;
                LDSM4(b0, b1, b2, b3, sWu + (PB[pr] ^ (kk << 5)));
                #pragma unroll
                for (int t = 0; t < 4; t++){
                    MMA16816(acc[t][pr][0], acc[t][pr][1], acc[t][pr][2], acc[t][pr][3],
                             a[t][0], a[t][1], a[t][2], a[t][3], b0, b1);
                    MMA16816(acc[t][pr][4], acc[t][pr][5], acc[t][pr][6], acc[t][pr][7],
                             a[t][0], a[t][1], a[t][2], a[t][3], b2, b3);
                }
            }
        }

        // ---- tgt gather (fp32) + tt partials ----
        float tg[2][16];
        float tts[2] = {0.f, 0.f};
        #pragma unroll
        for (int s = 0; s < 2; s++){
            int nl = rq + s * 8;
            int gn = n0 + nl;
            if (gn < Ntot){
                const float* tp = out_emb + (size_t)nodes[gn] * 256;
                #pragma unroll
                for (int pr = 0; pr < 4; pr++){
                    int cb = nw * 64 + pr * 16 + q * 2;
                    float2 v0 = *(const float2*)(tp + cb);
                    float2 v1 = *(const float2*)(tp + cb + 8);
                    tg[s][pr * 4 + 0] = v0.x; tg[s][pr * 4 + 1] = v0.y;
                    tg[s][pr * 4 + 2] = v1.x; tg[s][pr * 4 + 3] = v1.y;
                    tts[s] += v0.x * v0.x + v0.y * v0.y + v1.x * v1.x + v1.y * v1.y;
                }
            } else {
                #pragma unroll
                for (int j = 0; j < 16; j++) tg[s][j] = 0.f;
            }
        }
        if (mwarp == 0){
            #pragma unroll
            for (int s = 0; s < 2; s++){
                float v = tts[s];
                v += __shfl_xor_sync(0xFFFFFFFFu, v, 1);
                v += __shfl_xor_sync(0xFFFFFFFFu, v, 2);
                if (q == 0) sTT[(rq + s * 8) * 4 + nw] = v;
            }
        }

        // ---- epilogue: bias + tanh + num/hh, quad reduce, stash ----
        #pragma unroll
        for (int t = 0; t < 4; t++){
            const int mrow = mwarp * 4 + t;
            #pragma unroll
            for (int s = 0; s < 2; s++){
                float nm = 0.f, hv = 0.f;
                #pragma unroll
                for (int pr = 0; pr < 4; pr++){
                    int cb = nw * 64 + pr * 16 + q * 2;
                    float2 bb0 = *(const float2*)(fB + cb);
                    float2 bb1 = *(const float2*)(fB + cb + 8);
                    float h0 = tanha(acc[t][pr][s * 2 + 0] + bb0.x);
                    float h1 = tanha(acc[t][pr][s * 2 + 1] + bb0.y);
                    float h2 = tanha(acc[t][pr][4 + s * 2 + 0] + bb1.x);
                    float h3 = tanha(acc[t][pr][4 + s * 2 + 1] + bb1.y);
                    nm += h0 * tg[s][pr * 4 + 0] + h1 * tg[s][pr * 4 + 1]
                        + h2 * tg[s][pr * 4 + 2] + h3 * tg[s][pr * 4 + 3];
                    hv += h0 * h0 + h1 * h1 + h2 * h2 + h3 * h3;
                }
                nm += __shfl_xor_sync(0xFFFFFFFFu, nm, 1);
                nm += __shfl_xor_sync(0xFFFFFFFFu, nm, 2);
                hv += __shfl_xor_sync(0xFFFFFFFFu, hv, 1);
                hv += __shfl_xor_sync(0xFFFFFFFFu, hv, 2);
                if (q == 0){
                    int row = mrow * 16 + rq + s * 8;
                    sNum[row * 4 + nw] = nm;
                    sHh [row * 4 + nw] = hv;
                }
            }
        }

        __syncthreads();
        // ---- softmax over meta-paths, one thread per node -> sAtt ----
        if (tid < TILE_N && n0 + tid < Ntot){
            const int node = tid;
            float tt = sTT[node * 4] + sTT[node * 4 + 1] + sTT[node * 4 + 2] + sTT[node * 4 + 3];
            float tn = fmaxf(sqrtf(tt), EPSV);
            float cv[MPATH], mx = -1e30f;
            #pragma unroll
            for (int m = 0; m < MPATH; m++){
                int row = m * 16 + node;
                float num = sNum[row * 4] + sNum[row * 4 + 1] + sNum[row * 4 + 2] + sNum[row * 4 + 3];
                float hh  = sHh [row * 4] + sHh [row * 4 + 1] + sHh [row * 4 + 2] + sHh [row * 4 + 3];
                float hn = fmaxf(sqrtf(hh), EPSV);
                cv[m] = num / (hn * tn);
                mx = fmaxf(mx, cv[m]);
            }
            float se = 0.f;
            #pragma unroll
            for (int m = 0; m < MPATH; m++){ cv[m] = __expf(cv[m] - mx); se += cv[m]; }
            float inv = 1.f / se;
            #pragma unroll
            for (int m = 0; m < MPATH; m++) sAtt[node * 8 + m] = cv[m] * inv;
        }
        __syncthreads();

        // ---- fused weighted sum: out[n,:] = sum_m att * homo (fp32, L2-hot) ----
        {
            const int nl = tid >> 4;           // 0..15 node
            const int dc = tid & 15;           // 16-float chunk
            const int gn = n0 + nl;
            if (gn < Ntot){
                float att[MPATH];
                #pragma unroll
                for (int m = 0; m < MPATH; m++) att[m] = sAtt[nl * 8 + m];
                float4 a4[4];
                #pragma unroll
                for (int j = 0; j < 4; j++) a4[j] = make_float4(0.f, 0.f, 0.f, 0.f);
                #pragma unroll
                for (int m = 0; m < MPATH; m++){
                    const float4* hp = (const float4*)(homo + ((size_t)m * Ntot + gn) * 256 + dc * 16);
                    #pragma unroll
                    for (int j = 0; j < 4; j++){
                        float4 v = hp[j];
                        a4[j].x += att[m] * v.x; a4[j].y += att[m] * v.y;
                        a4[j].z += att[m] * v.z; a4[j].w += att[m] * v.w;
                    }
                }
                float4* op = (float4*)(out + (size_t)gn * 256 + dc * 16);
                #pragma unroll
                for (int j = 0; j < 4; j++) op[j] = a4[j];
            }
        }
        // next tile's stage-A sync doubles as the ws completion barrier
    }
}

extern "C" void kernel_launch(void* const* d_in, const int* in_sizes, int n_in,
                              void* d_out, int out_size){
    const int*   nodes = (const int*)  d_in[0];
    const float* homo  = (const float*)d_in[1];
    const float* W     = (const float*)d_in[2];
    const float* bias  = (const float*)d_in[3];
    const float* oe    = (const float*)d_in[4];
    float* out = (float*)d_out;
    const int N = in_sizes[0];

    prep_W<<<128, 256>>>(W);

    cudaFuncSetAttribute(hete_fused_kernel,
                         cudaFuncAttributeMaxDynamicSharedMemorySize, SMEM_BYTES);
    hete_fused_kernel<<<GRID, THREADS, SMEM_BYTES>>>(nodes, homo, bias, oe, out, N);
}

// round 9
// speedup vs baseline: 1.4889x; 1.1991x over previous
#include <cuda_runtime.h>
#include <cuda_bf16.h>
#include <cstdint>

#define MPATH 8
#define TILE_N 16
#define THREADS 512
#define GRID 148
#define EPSV 1e-8f

// smem byte offsets from 1024-aligned base
#define OFF_W    0         // 128 KB  W bf16 swizzled [256 h rows x 512B]
#define OFF_BF   131072    // 64 KB   A bf16 swizzled [128 rows = m*16+nl][512B]
#define OFF_NUM  196608    // 128*8 f32 = 4KB
#define OFF_HH   200704    // 4KB
#define OFF_TT   204800    // 16*8 f32 = 512B
#define OFF_ATT  205312    // 16*8 f32 = 512B
#define SMEM_BYTES (205824 + 1024)

__device__ unsigned int Wq_g[32768];   // bf16 W row-major pairs

__device__ __forceinline__ uint32_t s2u(const void* p){
    uint32_t a;
    asm("{ .reg .u64 t; cvta.to.shared.u64 t, %1; cvt.u32.u64 %0, t; }" : "=r"(a) : "l"(p));
    return a;
}
__device__ __forceinline__ uint32_t pbf2(float a, float b){
    __nv_bfloat162 v = __floats2bfloat162_rn(a, b);
    return *reinterpret_cast<uint32_t*>(&v);
}
__device__ __forceinline__ float tanha(float x){
    float r; asm("tanh.approx.f32 %0, %1;" : "=f"(r) : "f"(x)); return r;
}
#define LDSM4(r0,r1,r2,r3,addr) \
    asm volatile("ldmatrix.sync.aligned.m8n8.x4.shared.b16 {%0,%1,%2,%3}, [%4];" \
        : "=r"(r0), "=r"(r1), "=r"(r2), "=r"(r3) : "r"(addr))
#define MMA16816(c0,c1,c2,c3,a0,a1,a2,a3,b0,b1) \
    asm volatile("mma.sync.aligned.m16n8k16.row.col.f32.bf16.bf16.f32 " \
        "{%0,%1,%2,%3}, {%4,%5,%6,%7}, {%8,%9}, {%0,%1,%2,%3};" \
        : "+f"(c0), "+f"(c1), "+f"(c2), "+f"(c3) \
        : "r"(a0), "r"(a1), "r"(a2), "r"(a3), "r"(b0), "r"(b1))

__global__ void prep_W(const float* __restrict__ W){
    int p = blockIdx.x * blockDim.x + threadIdx.x;   // 0..32767
    int h = p >> 7, d = (p & 127) * 2;
    Wq_g[p] = pbf2(W[h * 256 + d], W[h * 256 + d + 1]);
}

__global__ __launch_bounds__(THREADS, 1)
void hete_fused_kernel(const int* __restrict__ nodes,
                       const float* __restrict__ homo,
                       const float* __restrict__ bias,
                       const float* __restrict__ out_emb,
                       float* __restrict__ out,
                       int Ntot){
    extern __shared__ unsigned char smraw[];
    unsigned char* base = (unsigned char*)(((uintptr_t)smraw + 1023) & ~(uintptr_t)1023);

    const int tid  = threadIdx.x;
    const int lane = tid & 31;
    const int wid  = tid >> 5;
    const int mw   = wid >> 3;        // 0..1   row half: rows mw*64..+63
    const int nw   = wid & 7;         // 0..7   cols nw*32..+31
    const int q    = lane & 3;
    const int g    = lane >> 2;       // 0..7

    float* sNum = (float*)(base + OFF_NUM);
    float* sHh  = (float*)(base + OFF_HH);
    float* sTT  = (float*)(base + OFF_TT);
    float* sAtt = (float*)(base + OFF_ATT);
    const uint32_t sWu  = s2u(base + OFF_W);
    const uint32_t sBFu = s2u(base + OFF_BF);

    const int ntiles = (Ntot + TILE_N - 1) / TILE_N;

    // ---- stage W once ----
    {
        const uint4* gw = (const uint4*)Wq_g;
        #pragma unroll
        for (int i = 0; i < 16; i++){
            int idx = i * 512 + tid;
            int row = idx >> 5, c = idx & 31;
            *(uint4*)(base + OFF_W + row * 512 + ((c ^ (row & 7)) << 4)) = gw[idx];
        }
    }

    // ---- bias in registers: cols nw*32 + pr*8 + q*2 ----
    float2 bb[4];
    #pragma unroll
    for (int pr = 0; pr < 4; pr++)
        bb[pr] = *(const float2*)(bias + nw * 32 + pr * 8 + q * 2);

    // ---- ldmatrix base addresses ----
    const int arow = mw * 64 + (lane & 15);       // + t*16 per 16-row group
    const uint32_t PA0 = (uint32_t)(arow * 512) ^
                         ((uint32_t)((((lane & 7)) ^ (lane >> 4)) << 4));
    uint32_t PB[2];
    #pragma unroll
    for (int pp = 0; pp < 2; pp++){
        int brow = nw * 32 + pp * 16 + ((lane & 16) >> 1) + (lane & 7);
        int hi = (lane >> 3) & 1;
        PB[pp] = (uint32_t)(brow * 512) ^ ((uint32_t)(((brow & 7) ^ hi) << 4));
    }

    for (int tile = blockIdx.x; tile < ntiles; tile += GRID){
        const int n0 = tile * TILE_N;

        // ---- stage A: homo[m, n0+nl, :] fp32 -> bf16 swizzled (row = m*16+nl) ----
        #pragma unroll
        for (int i = 0; i < 16; i++){
            int gi = i * 512 + tid;               // 0..8191 float4 index
            int row = gi >> 6, d4 = gi & 63;
            int m = row >> 4, nl = row & 15;
            float4 v = make_float4(0.f, 0.f, 0.f, 0.f);
            if (n0 + nl < Ntot)
                v = *(const float4*)(homo + ((size_t)m * Ntot + (n0 + nl)) * 256 + d4 * 4);
            uint32_t phys = (uint32_t)(row * 512)
                          + ((((uint32_t)(d4 >> 1) ^ (uint32_t)(row & 7)) << 4))
                          + (uint32_t)(d4 & 1) * 8;
            uint2 o; o.x = pbf2(v.x, v.y); o.y = pbf2(v.z, v.w);
            *(uint2*)(base + OFF_BF + phys) = o;
        }
        __syncthreads();   // (A) bf16 tile ready; prior softmax reads of sNum done

        // ---- tgt gather: nodes g and g+8, 8 cols each (hidden under MMA) ----
        float2 tgA[4], tgB[4];
        float ttA = 0.f, ttB = 0.f;
        {
            int gn = n0 + g;
            if (gn < Ntot){
                const float* tp = out_emb + (size_t)nodes[gn] * 256 + nw * 32 + q * 2;
                #pragma unroll
                for (int pr = 0; pr < 4; pr++){
                    tgA[pr] = *(const float2*)(tp + pr * 8);
                    ttA += tgA[pr].x * tgA[pr].x + tgA[pr].y * tgA[pr].y;
                }
            } else {
                #pragma unroll
                for (int pr = 0; pr < 4; pr++) tgA[pr] = make_float2(0.f, 0.f);
            }
            gn = n0 + g + 8;
            if (gn < Ntot){
                const float* tp = out_emb + (size_t)nodes[gn] * 256 + nw * 32 + q * 2;
                #pragma unroll
                for (int pr = 0; pr < 4; pr++){
                    tgB[pr] = *(const float2*)(tp + pr * 8);
                    ttB += tgB[pr].x * tgB[pr].x + tgB[pr].y * tgB[pr].y;
                }
            } else {
                #pragma unroll
                for (int pr = 0; pr < 4; pr++) tgB[pr] = make_float2(0.f, 0.f);
            }
        }

        // ---- MMA: warp = 64 rows x 32 cols, K=256 ----
        float acc[4][4][4];
        #pragma unroll
        for (int t = 0; t < 4; t++)
            #pragma unroll
            for (int pr = 0; pr < 4; pr++)
                #pragma unroll
                for (int c = 0; c < 4; c++) acc[t][pr][c] = 0.f;

        #pragma unroll 4
        for (int kk = 0; kk < 16; kk++){
            uint32_t a[4][4];
            #pragma unroll
            for (int t = 0; t < 4; t++)
                LDSM4(a[t][0], a[t][1], a[t][2], a[t][3],
                      sBFu + ((PA0 + t * 8192) ^ (kk << 5)));
            #pragma unroll
            for (int pp = 0; pp < 2; pp++){
                uint32_t b0, b1, b2, b3;
                LDSM4(b0, b1, b2, b3, sWu + (PB[pp] ^ (kk << 5)));
                #pragma unroll
                for (int t = 0; t < 4; t++){
                    MMA16816(acc[t][2*pp][0],   acc[t][2*pp][1],   acc[t][2*pp][2],   acc[t][2*pp][3],
                             a[t][0], a[t][1], a[t][2], a[t][3], b0, b1);
                    MMA16816(acc[t][2*pp+1][0], acc[t][2*pp+1][1], acc[t][2*pp+1][2], acc[t][2*pp+1][3],
                             a[t][0], a[t][1], a[t][2], a[t][3], b2, b3);
                }
            }
        }

        // ---- tt partials (only mw==0 stores; mw==1 duplicates) ----
        {
            float v = ttA;
            v += __shfl_xor_sync(0xFFFFFFFFu, v, 1);
            v += __shfl_xor_sync(0xFFFFFFFFu, v, 2);
            float w = ttB;
            w += __shfl_xor_sync(0xFFFFFFFFu, w, 1);
            w += __shfl_xor_sync(0xFFFFFFFFu, w, 2);
            if (mw == 0 && q == 0){
                sTT[g * 8 + nw]       = v;
                sTT[(g + 8) * 8 + nw] = w;
            }
        }

        // ---- epilogue: per t (m = mw*4+t), nodes g (c0,c1) and g+8 (c2,c3) ----
        #pragma unroll
        for (int t = 0; t < 4; t++){
            const int m = mw * 4 + t;
            float nmA = 0.f, hvA = 0.f, nmB = 0.f, hvB = 0.f;
            #pragma unroll
            for (int pr = 0; pr < 4; pr++){
                float h0 = tanha(acc[t][pr][0] + bb[pr].x);
                float h1 = tanha(acc[t][pr][1] + bb[pr].y);
                nmA += h0 * tgA[pr].x + h1 * tgA[pr].y;
                hvA += h0 * h0 + h1 * h1;
                float h2 = tanha(acc[t][pr][2] + bb[pr].x);
                float h3 = tanha(acc[t][pr][3] + bb[pr].y);
                nmB += h2 * tgB[pr].x + h3 * tgB[pr].y;
                hvB += h2 * h2 + h3 * h3;
            }
            nmA += __shfl_xor_sync(0xFFFFFFFFu, nmA, 1); nmA += __shfl_xor_sync(0xFFFFFFFFu, nmA, 2);
            hvA += __shfl_xor_sync(0xFFFFFFFFu, hvA, 1); hvA += __shfl_xor_sync(0xFFFFFFFFu, hvA, 2);
            nmB += __shfl_xor_sync(0xFFFFFFFFu, nmB, 1); nmB += __shfl_xor_sync(0xFFFFFFFFu, nmB, 2);
            hvB += __shfl_xor_sync(0xFFFFFFFFu, hvB, 1); hvB += __shfl_xor_sync(0xFFFFFFFFu, hvB, 2);
            if (q == 0){
                sNum[(m * 16 + g) * 8 + nw]       = nmA;
                sNum[(m * 16 + g + 8) * 8 + nw]   = nmB;
                sHh [(m * 16 + g) * 8 + nw]       = hvA;
                sHh [(m * 16 + g + 8) * 8 + nw]   = hvB;
            }
        }

        __syncthreads();   // (C) partials visible

        // ---- softmax over meta-paths, one thread per node ----
        if (tid < TILE_N && n0 + tid < Ntot){
            const int node = tid;
            float tt = 0.f;
            #pragma unroll
            for (int w = 0; w < 8; w++) tt += sTT[node * 8 + w];
            float tn = fmaxf(sqrtf(tt), EPSV);
            float cv[MPATH], mx = -1e30f;
            #pragma unroll
            for (int m = 0; m < MPATH; m++){
                int row = m * 16 + node;
                float num = 0.f, hh = 0.f;
                #pragma unroll
                for (int w = 0; w < 8; w++){ num += sNum[row * 8 + w]; hh += sHh[row * 8 + w]; }
                float hn = fmaxf(sqrtf(hh), EPSV);
                cv[m] = num / (hn * tn);
                mx = fmaxf(mx, cv[m]);
            }
            float se = 0.f;
            #pragma unroll
            for (int m = 0; m < MPATH; m++){ cv[m] = __expf(cv[m] - mx); se += cv[m]; }
            float inv = 1.f / se;
            #pragma unroll
            for (int m = 0; m < MPATH; m++) sAtt[node * 8 + m] = cv[m] * inv;
        }
        __syncthreads();   // (D) sAtt ready

        // ---- fused weighted sum (homo via L2-hot gmem) ----
        {
            const int nl = tid >> 5;          // 0..15
            const int d8 = tid & 31;          // 8-float chunk
            const int gn = n0 + nl;
            if (gn < Ntot){
                float att[MPATH];
                #pragma unroll
                for (int m = 0; m < MPATH; m++) att[m] = sAtt[nl * 8 + m];
                float4 a0 = make_float4(0.f, 0.f, 0.f, 0.f);
                float4 a1 = make_float4(0.f, 0.f, 0.f, 0.f);
                #pragma unroll
                for (int m = 0; m < MPATH; m++){
                    const float4* hp = (const float4*)(homo + ((size_t)m * Ntot + gn) * 256 + d8 * 8);
                    float4 v0 = hp[0], v1 = hp[1];
                    a0.x += att[m] * v0.x; a0.y += att[m] * v0.y;
                    a0.z += att[m] * v0.z; a0.w += att[m] * v0.w;
                    a1.x += att[m] * v1.x; a1.y += att[m] * v1.y;
                    a1.z += att[m] * v1.z; a1.w += att[m] * v1.w;
                }
                float4* op = (float4*)(out + (size_t)gn * 256 + d8 * 8);
                op[0] = a0; op[1] = a1;
            }
        }
        // next tile's barrier (A) protects the bf16 buffer and sAtt
    }
}

extern "C" void kernel_launch(void* const* d_in, const int* in_sizes, int n_in,
                              void* d_out, int out_size){
    const int*   nodes = (const int*)  d_in[0];
    const float* homo  = (const float*)d_in[1];
    const float* W     = (const float*)d_in[2];
    const float* bias  = (const float*)d_in[3];
    const float* oe    = (const float*)d_in[4];
    float* out = (float*)d_out;
    const int N = in_sizes[0];

    prep_W<<<128, 256>>>(W);

    cudaFuncSetAttribute(hete_fused_kernel,
                         cudaFuncAttributeMaxDynamicSharedMemorySize, SMEM_BYTES);
    hete_fused_kernel<<<GRID, THREADS, SMEM_BYTES>>>(nodes, homo, bias, oe, out, N);
}